// round 13
// baseline (speedup 1.0000x reference)
#include <cuda_runtime.h>
#include <cstdint>

namespace {

constexpr int KNUM  = 32;           // pole pairs total (64 poles as 32 conj pairs)
constexpr int KP    = 4;            // packed pairs-of-poles per THREAD (8 poles)
constexpr int DDIM  = 1024;
constexpr int LLEN  = 2048;
constexpr int CHUNK = 64;           // output elements per thread
constexpr int NCH   = LLEN / CHUNK; // 32 chunks per row

using u64 = unsigned long long;

// ---- packed f32x2 primitives (sm_103a dual-lane fp32 path) ----
__device__ __forceinline__ u64 pk2(float lo, float hi) {
    u64 r; asm("mov.b64 %0, {%1, %2};" : "=l"(r) : "f"(lo), "f"(hi)); return r;
}
__device__ __forceinline__ void unpk2(u64 v, float& lo, float& hi) {
    asm("mov.b64 {%0, %1}, %2;" : "=f"(lo), "=f"(hi) : "l"(v));
}
__device__ __forceinline__ u64 add2(u64 a, u64 b) {
    u64 d; asm("add.rn.f32x2 %0, %1, %2;" : "=l"(d) : "l"(a), "l"(b)); return d;
}
__device__ __forceinline__ u64 mul2(u64 a, u64 b) {
    u64 d; asm("mul.rn.f32x2 %0, %1, %2;" : "=l"(d) : "l"(a), "l"(b)); return d;
}
__device__ __forceinline__ u64 fma2(u64 a, u64 b, u64 c) {
    u64 d; asm("fma.rn.f32x2 %0, %1, %2, %3;" : "=l"(d) : "l"(a), "l"(b), "l"(c)); return d;
}
__device__ __forceinline__ float fast_lg2(float x) {
    float y; asm("lg2.approx.f32 %0, %1;" : "=f"(y) : "f"(x)); return y;
}
__device__ __forceinline__ float fast_ex2(float x) {
    float y; asm("ex2.approx.f32 %0, %1;" : "=f"(y) : "f"(x)); return y;
}

// Split-K=4 decomposition. Warp = (d, 8 chunks x 4 pole-quarters):
//   lane = q*8 + c3   (q = lane>>3: pole quarter, c3 = lane&7: chunk-in-warp)
//   c = (warp&3)*8 + c3  (32 chunks of 64 taps per row), d = warp>>2.
// Each thread runs 4 packed pairs (8 poles); butterfly shfl_xor(8) + shfl_xor(16)
// merges the 4 quarter-partials; lanes q==0 store.
//
// SOFTWARE PIPELINE: each output's two 26-cyc shfl latencies are hidden by
// issuing the xor-8 shfl one stage early (right after the partial that feeds it)
// and consuming the xor-16 result only after the 8-f32x2 advance of the same
// step. Critical path per output drops from ~70 exposed cycles to ~0.
//
// Recurrence per pole: x(t+1) = a*x(t) + b*x(t-1), a = 2 r cos(theta),
// b = -r^2, packed 2 poles per f32x2. Chunk starts re-anchored from closed form
// (all-float, twoprod + Cody-Waite phase reduction): no >64-step error growth.
__global__ void __launch_bounds__(64, 13)
modal_filter_kernel(const float* __restrict__ rr_,
                    const float* __restrict__ th_,
                    const float* __restrict__ Rre_,
                    const float* __restrict__ Rim_,
                    const float* __restrict__ h0_,
                    float* __restrict__ out)
{
    const int gtid = blockIdx.x * 64 + threadIdx.x;
    const int warp = gtid >> 5;
    const int lane = gtid & 31;
    const int d    = warp >> 2;                        // channel row (warp-uniform)
    const int c    = ((warp & 3) << 3) + (lane & 7);   // chunk 0..31
    const int q    = lane >> 3;                        // pole quarter 0..3

    // Output window [64c, 64c+64). Output j maps to series index t = j-1
    // (j = 0 is h_0), so this chunk's series starts at t0 = 64c - 1.
    const float t0f = (float)(CHUNK * c - 1);

    u64 A[KP], B[KP], X[KP], XM[KP];

    #pragma unroll
    for (int kp = 0; kp < KP; kp++) {
        float av[2], bv[2], x0[2], x1[2];
        #pragma unroll
        for (int j = 0; j < 2; j++) {
            const int k = q * 8 + kp * 2 + j;
            const float rv = __ldg(&rr_ [k * DDIM + d]);
            const float tv = __ldg(&th_ [k * DDIM + d]);
            const float Rr = __ldg(&Rre_[k * DDIM + d]);
            const float Ri = __ldg(&Rim_[k * DDIM + d]);

            float sT, cT;
            __sincosf(tv, &sT, &cT);             // arg in [0, 2pi): fast path fine
            const float pre = rv * cT;
            const float pim = rv * sT;
            av[j] = pre + pre;                   // 2 r cos(theta)
            bv[j] = -(rv * rv);                  // -r^2

            // amp = r^t0 via MUFU lg2/ex2. Exponent abs err <= |t0|*2^-22:
            // only meaningful where amp ~1 (small t0) -> <1e-5 output impact.
            const float amp = fast_ex2(t0f * fast_lg2(rv));

            // phase = t0*theta mod 2pi, all-float: exact twoprod, then 2-constant
            // Cody-Waite. Residual ~1e-6 rad.
            const float hi = t0f * tv;
            const float lo = __fmaf_rn(t0f, tv, -hi);     // exact residual
            const float nn = rintf(hi * 0.15915494309f);  // 1/(2pi)
            float red = __fmaf_rn(nn, -6.28125f, hi);     // 2pi hi (13-bit exact)
            red = __fmaf_rn(nn, -1.9353071795864769e-3f, red); // 2pi - 6.28125
            red += lo;
            float sA, cA;
            __sincosf(red, &sA, &cA);

            const float wre = amp * (Rr * cA - Ri * sA);   // Re(R p^t0)
            const float wim = amp * (Rr * sA + Ri * cA);   // Im(R p^t0)
            x0[j] = wre;                                   // x(t0)
            x1[j] = wre * pre - wim * pim;                 // x(t0+1)
        }
        A[kp]  = pk2(av[0], av[1]);
        B[kp]  = pk2(bv[0], bv[1]);
        XM[kp] = pk2(x0[0], x0[1]);
        X[kp]  = pk2(x1[0], x1[1]);
    }

    float* op = out + (size_t)d * LLEN + c * CHUNK;
    const float h0d = __ldg(&h0_[d]);

    // ---- pipeline prologue: partial + first butterfly stage for output 0 ----
    float part, s1;
    {
        const u64 s = add2(add2(XM[0], XM[1]), add2(XM[2], XM[3]));
        float slo, shi; unpk2(s, slo, shi);
        part = slo + shi;
        s1 = __shfl_xor_sync(0xFFFFFFFFu, part, 8);
    }

    #pragma unroll 1
    for (int i = 0; i < CHUNK; i += 4) {
        float buf[4];
        #pragma unroll
        for (int j = 0; j < 4; j++) {
            // finish stage 1 of output (i+j); issue stage 2
            const float p2 = part + s1;
            const float s2 = __shfl_xor_sync(0xFFFFFFFFu, p2, 16);

            // advance the 8 recurrences (8 f32x2) — hides the xor-16 latency
            #pragma unroll
            for (int kp = 0; kp < KP; kp++) {
                const u64 xn = fma2(A[kp], X[kp], mul2(B[kp], XM[kp]));
                XM[kp] = X[kp];
                X[kp]  = xn;
            }

            // next output's partial + stage-1 shfl (hides its own latency)
            const u64 s = add2(add2(XM[0], XM[1]), add2(XM[2], XM[3]));
            float slo, shi; unpk2(s, slo, shi);
            const float pn  = slo + shi;
            const float s1n = __shfl_xor_sync(0xFFFFFFFFu, pn, 8);

            buf[j] = p2 + s2;                 // consume stage 2 (latency covered)
            part = pn; s1 = s1n;
        }
        if (i == 0 && c == 0) buf[0] = h0d;   // output position j=0 is h_0[d]
        if (q == 0) {                         // one lane per chunk stores
            float4 v; v.x = buf[0]; v.y = buf[1]; v.z = buf[2]; v.w = buf[3];
            *reinterpret_cast<float4*>(op + i) = v;   // 16B aligned: 64c + 4i
        }
    }
}

} // namespace

extern "C" void kernel_launch(void* const* d_in, const int* in_sizes, int n_in,
                              void* d_out, int out_size) {
    const float* rr  = (const float*)d_in[0];   // r      (K, D)
    const float* th  = (const float*)d_in[1];   // theta  (K, D)
    const float* Rre = (const float*)d_in[2];   // R_re   (K, D)
    const float* Rim = (const float*)d_in[3];   // R_im   (K, D)
    const float* h0  = (const float*)d_in[4];   // h_0    (1, D)
    (void)in_sizes; (void)n_in; (void)out_size; // shapes fixed: K=32, D=1024, L=2048

    // 1024 rows x 32 chunks x 4 pole-quarters = 131072 threads = 2048 blocks of 64.
    modal_filter_kernel<<<(DDIM * NCH * 4) / 64, 64>>>(
        rr, th, Rre, Rim, h0, (float*)d_out);
}

// round 15
// speedup vs baseline: 1.0991x; 1.0991x over previous
#include <cuda_runtime.h>
#include <cstdint>

namespace {

constexpr int DDIM  = 1024;
constexpr int LLEN  = 2048;
constexpr int CHUNK = 32;           // output elements per thread
constexpr int NCH   = LLEN / CHUNK; // 64 chunks per row
constexpr int NU    = 4;            // packed quad-units per thread
                                    // (unit = f32x2 of 2 groups; group = 2 pole pairs)

using u64 = unsigned long long;

// ---- packed f32x2 primitives (sm_103a dual-lane fp32 path) ----
__device__ __forceinline__ u64 pk2(float lo, float hi) {
    u64 r; asm("mov.b64 %0, {%1, %2};" : "=l"(r) : "f"(lo), "f"(hi)); return r;
}
__device__ __forceinline__ void unpk2(u64 v, float& lo, float& hi) {
    asm("mov.b64 {%0, %1}, %2;" : "=f"(lo), "=f"(hi) : "l"(v));
}
__device__ __forceinline__ u64 add2(u64 a, u64 b) {
    u64 d; asm("add.rn.f32x2 %0, %1, %2;" : "=l"(d) : "l"(a), "l"(b)); return d;
}
__device__ __forceinline__ u64 mul2(u64 a, u64 b) {
    u64 d; asm("mul.rn.f32x2 %0, %1, %2;" : "=l"(d) : "l"(a), "l"(b)); return d;
}
__device__ __forceinline__ u64 fma2(u64 a, u64 b, u64 c) {
    u64 d; asm("fma.rn.f32x2 %0, %1, %2, %3;" : "=l"(d) : "l"(a), "l"(b), "l"(c)); return d;
}
__device__ __forceinline__ float fast_lg2(float x) {
    float y; asm("lg2.approx.f32 %0, %1;" : "=f"(y) : "f"(x)); return y;
}
__device__ __forceinline__ float fast_ex2(float x) {
    float y; asm("ex2.approx.f32 %0, %1;" : "=f"(y) : "f"(x)); return y;
}

// Split-2 geometry (R6): warp = one d; lane = half*16 + (chunk&15);
// c = (warp&3)*16 + (lane&15) covers 64 chunks; half owns 16 pole pairs.
//
// ORDER-4 RECURRENCES: each group of 2 pole pairs is collapsed into one
// order-4 real recurrence on the SUM of their contributions:
//   x(t) = e1 x(t-1) + e2 x(t-2) + e3 x(t-3) + e4 x(t-4)
//   e1 = a1+a2, e2 = b1+b2-a1*a2, e3 = -(a1*b2+a2*b1), e4 = -b1*b2
// (product of the two order-2 characteristic polynomials). This halves the
// per-output sum tree (states are pre-summed) at identical advance flops,
// and the first 4 outputs of each chunk come free from the init states.
// 8 groups/thread packed as 4 f32x2 quad-units (lo/hi = 2 groups).
__global__ void __launch_bounds__(64, 10)
modal_filter_kernel(const float* __restrict__ rr_,
                    const float* __restrict__ th_,
                    const float* __restrict__ Rre_,
                    const float* __restrict__ Rim_,
                    const float* __restrict__ h0_,
                    float* __restrict__ out)
{
    const int gtid = blockIdx.x * 64 + threadIdx.x;
    const int warp = gtid >> 5;
    const int lane = gtid & 31;
    const int d    = warp >> 2;                        // channel row (warp-uniform)
    const int c    = ((warp & 3) << 4) + (lane & 15);  // chunk 0..63
    const int half = lane >> 4;                        // pole half (16 pairs each)

    // Output j = 32c+s maps to series index t = t0+s, t0 = 32c-1 (j=0 is h_0).
    const float t0f = (float)(CHUNK * c - 1);

    u64 E1[NU], E2[NU], E3[NU], E4[NU];   // order-4 coeffs (packed 2 groups)
    u64 Ya[NU], Yb[NU], Yc[NU], Yd[NU];   // states x(t0+0..3)   (packed)

    #pragma unroll
    for (int u = 0; u < NU; u++) {
        float e1v[2], e2v[2], e3v[2], e4v[2], s0v[2], s1v[2], s2v[2], s3v[2];
        #pragma unroll
        for (int j = 0; j < 2; j++) {                  // group g = 2u+j
            const int g = u * 2 + j;
            float ga[2], gb[2], gx0[2], gx1[2], gx2[2], gx3[2];
            #pragma unroll
            for (int pp = 0; pp < 2; pp++) {           // the group's 2 pole pairs
                const int k = half * 16 + g * 2 + pp;
                const float rv = __ldg(&rr_ [k * DDIM + d]);
                const float tv = __ldg(&th_ [k * DDIM + d]);
                const float Rr = __ldg(&Rre_[k * DDIM + d]);
                const float Ri = __ldg(&Rim_[k * DDIM + d]);

                float sT, cT;
                __sincosf(tv, &sT, &cT);           // arg in [0,2pi): fast path ok
                const float pre = rv * cT;
                const float pim = rv * sT;
                const float a = pre + pre;         // 2 r cos(theta)
                const float b = -(rv * rv);        // -r^2

                // amp = r^t0 via MUFU lg2/ex2 (err meaningful only where amp~1).
                const float amp = fast_ex2(t0f * fast_lg2(rv));

                // phase = t0*theta mod 2pi: exact twoprod + 2-term Cody-Waite.
                const float hi = t0f * tv;
                const float lo = __fmaf_rn(t0f, tv, -hi);
                const float nn = rintf(hi * 0.15915494309f);
                float red = __fmaf_rn(nn, -6.28125f, hi);
                red = __fmaf_rn(nn, -1.9353071795864769e-3f, red);
                red += lo;
                float sA, cA;
                __sincosf(red, &sA, &cA);

                const float wre = amp * (Rr * cA - Ri * sA);   // Re(R p^t0)
                const float wim = amp * (Rr * sA + Ri * cA);   // Im(R p^t0)
                const float x0 = wre;                          // x(t0)
                const float x1 = wre * pre - wim * pim;        // x(t0+1)
                const float x2 = __fmaf_rn(a, x1, b * x0);     // x(t0+2)
                const float x3 = __fmaf_rn(a, x2, b * x1);     // x(t0+3)
                ga[pp] = a; gb[pp] = b;
                gx0[pp] = x0; gx1[pp] = x1; gx2[pp] = x2; gx3[pp] = x3;
            }
            // order-4 coefficients for the pair-of-pairs
            e1v[j] = ga[0] + ga[1];
            e2v[j] = gb[0] + gb[1] - ga[0] * ga[1];
            e3v[j] = -(ga[0] * gb[1] + ga[1] * gb[0]);
            e4v[j] = -(gb[0] * gb[1]);
            // summed initial states
            s0v[j] = gx0[0] + gx0[1];
            s1v[j] = gx1[0] + gx1[1];
            s2v[j] = gx2[0] + gx2[1];
            s3v[j] = gx3[0] + gx3[1];
        }
        E1[u] = pk2(e1v[0], e1v[1]); E2[u] = pk2(e2v[0], e2v[1]);
        E3[u] = pk2(e3v[0], e3v[1]); E4[u] = pk2(e4v[0], e4v[1]);
        Ya[u] = pk2(s0v[0], s0v[1]); Yb[u] = pk2(s1v[0], s1v[1]);
        Yc[u] = pk2(s2v[0], s2v[1]); Yd[u] = pk2(s3v[0], s3v[1]);
    }

    float* op = out + (size_t)d * LLEN + c * CHUNK;
    const float h0d = __ldg(&h0_[d]);

    // merge: tree over 4 units, unpack, cross-half shfl
    auto merge = [&](const u64* w) -> float {
        const u64 s = add2(add2(w[0], w[1]), add2(w[2], w[3]));
        float slo, shi; unpk2(s, slo, shi);
        float p = slo + shi;
        p += __shfl_xor_sync(0xFFFFFFFFu, p, 16);
        return p;
    };

    // iteration 0: outputs s=0..3 straight from the init states
    {
        float buf[4];
        buf[0] = merge(Ya); buf[1] = merge(Yb);
        buf[2] = merge(Yc); buf[3] = merge(Yd);
        if (c == 0) buf[0] = h0d;             // output position j=0 is h_0[d]
        if (half == 0) {
            float4 v; v.x = buf[0]; v.y = buf[1]; v.z = buf[2]; v.w = buf[3];
            *reinterpret_cast<float4*>(op) = v;
        }
    }

    // iterations 1..7: 4 order-4 advances each, ring-rotated in place
    #pragma unroll
    for (int it = 1; it < 8; it++) {
        float buf[4];
        #pragma unroll
        for (int u = 0; u < NU; u++)
            Ya[u] = fma2(E1[u], Yd[u], fma2(E2[u], Yc[u],
                     fma2(E3[u], Yb[u], mul2(E4[u], Ya[u]))));
        buf[0] = merge(Ya);
        #pragma unroll
        for (int u = 0; u < NU; u++)
            Yb[u] = fma2(E1[u], Ya[u], fma2(E2[u], Yd[u],
                     fma2(E3[u], Yc[u], mul2(E4[u], Yb[u]))));
        buf[1] = merge(Yb);
        #pragma unroll
        for (int u = 0; u < NU; u++)
            Yc[u] = fma2(E1[u], Yb[u], fma2(E2[u], Ya[u],
                     fma2(E3[u], Yd[u], mul2(E4[u], Yc[u]))));
        buf[2] = merge(Yc);
        #pragma unroll
        for (int u = 0; u < NU; u++)
            Yd[u] = fma2(E1[u], Yc[u], fma2(E2[u], Yb[u],
                     fma2(E3[u], Ya[u], mul2(E4[u], Yd[u]))));
        buf[3] = merge(Yd);

        if (half == 0) {
            float4 v; v.x = buf[0]; v.y = buf[1]; v.z = buf[2]; v.w = buf[3];
            *reinterpret_cast<float4*>(op + it * 4) = v;
        }
    }
}

} // namespace

extern "C" void kernel_launch(void* const* d_in, const int* in_sizes, int n_in,
                              void* d_out, int out_size) {
    const float* rr  = (const float*)d_in[0];   // r      (K, D)
    const float* th  = (const float*)d_in[1];   // theta  (K, D)
    const float* Rre = (const float*)d_in[2];   // R_re   (K, D)
    const float* Rim = (const float*)d_in[3];   // R_im   (K, D)
    const float* h0  = (const float*)d_in[4];   // h_0    (1, D)
    (void)in_sizes; (void)n_in; (void)out_size; // shapes fixed: K=32, D=1024, L=2048

    // 1024 rows x 64 chunks x 2 pole-halves = 131072 threads = 2048 blocks of 64
    modal_filter_kernel<<<(DDIM * NCH * 2) / 64, 64>>>(
        rr, th, Rre, Rim, h0, (float*)d_out);
}